// round 13
// baseline (speedup 1.0000x reference)
#include <cuda_runtime.h>
#include <cuda_fp16.h>
#include <cstdint>

// out[M,N] = X[M,K] @ Wq[N,K]^T, Wq = sign(W)*max(scales,1e-8), groups of 128 along K
#define MDIM 8192
#define NDIM 4096
#define KDIM 4096

#define TM 128
#define TN 128
#define TKH 64                       // halves per K stage (one 128B panel per row)
#define NSTAGE 3
#define KSTAGES (KDIM / TKH)         // 64

#define A_BYTES (TM * 128)           // 16384 per stage
#define B_BYTES (TN * 128)           // 16384 per stage
#define STAGE_BYTES (A_BYTES + B_BYTES)        // 32768
#define SMEM_BYTES (NSTAGE * STAGE_BYTES + 64) // 98368 -> 2 CTAs/SM

#define NTHREADS 128

#define XBLOCKS (MDIM * KDIM * 2 / 16 / 256)   // 16384
#define WBLOCKS (NDIM * KDIM * 2 / 16 / 256)   // 8192

// Pre-swizzled tile-major operand images (exact smem byte image per (tile,stage)).
__device__ __align__(16) __half g_Xh[(size_t)MDIM * KDIM];   // 64 MB
__device__ __align__(16) __half g_Wh[(size_t)NDIM * KDIM];   // 32 MB

__device__ __forceinline__ uint32_t smem_u32(const void* p) {
    uint32_t a;
    asm("{ .reg .u64 t; cvta.to.shared.u64 t, %1; cvt.u32.u64 %0, t; }" : "=r"(a) : "l"(p));
    return a;
}

#define LDMATRIX_X4(r0, r1, r2, r3, addr)                                        \
    asm volatile("ldmatrix.sync.aligned.m8n8.x4.shared.b16 {%0,%1,%2,%3}, [%4];" \
                 : "=r"(r0), "=r"(r1), "=r"(r2), "=r"(r3) : "r"(addr))

#define MMA16816(c, a0, a1, a2, a3, b0, b1)                                      \
    asm volatile("mma.sync.aligned.m16n8k16.row.col.f32.f16.f16.f32 "            \
                 "{%0,%1,%2,%3}, {%4,%5,%6,%7}, {%8,%9}, {%0,%1,%2,%3};"         \
                 : "+f"((c)[0]), "+f"((c)[1]), "+f"((c)[2]), "+f"((c)[3])        \
                 : "r"(a0), "r"(a1), "r"(a2), "r"(a3), "r"(b0), "r"(b1))

#define MBAR_INIT(addr, cnt) \
    asm volatile("mbarrier.init.shared.b64 [%0], %1;" :: "r"(addr), "r"(cnt) : "memory")

#define MBAR_ARRIVE(addr) \
    asm volatile("mbarrier.arrive.shared.b64 _, [%0];" :: "r"(addr) : "memory")

#define CPASYNC_MBAR_ARRIVE(addr) \
    asm volatile("cp.async.mbarrier.arrive.noinc.shared.b64 [%0];" :: "r"(addr) : "memory")

// Non-blocking probe: result flag only, no branch (latency overlaps later work).
#define MBAR_TRY(res, addr, parity)                                               \
    asm volatile(                                                                 \
        "{\n\t.reg .pred p;\n\t"                                                  \
        "mbarrier.try_wait.parity.acquire.cta.shared::cta.b64 p, [%1], %2;\n\t"  \
        "selp.b32 %0, 1, 0, p;\n\t}"                                              \
        : "=r"(res) : "r"((uint32_t)(addr)), "r"((uint32_t)(parity)) : "memory")

#define MBAR_WAIT(mbar_addr, phase_parity) do {                                   \
    uint32_t _mbar = (uint32_t)(mbar_addr);                                       \
    uint32_t _parity = (uint32_t)(phase_parity);                                  \
    uint32_t _done;                                                               \
    asm volatile(                                                                 \
        "{\n\t.reg .pred p;\n\t"                                                  \
        "mbarrier.try_wait.parity.acquire.cta.shared::cta.b64 p, [%1], %2;\n\t"  \
        "selp.b32 %0, 1, 0, p;\n\t}"                                              \
        : "=r"(_done) : "r"(_mbar), "r"(_parity) : "memory");                     \
    if (!_done) {                                                                 \
        asm volatile(                                                             \
            "{\n\t.reg .pred P1;\n\t"                                             \
            "WAIT_LOOP_%=:\n\t"                                                   \
            "mbarrier.try_wait.parity.acquire.cta.shared::cta.b64 P1, [%0], %1, 0x989680;\n\t" \
            "@P1 bra.uni WAIT_DONE_%=;\n\t"                                       \
            "bra.uni WAIT_LOOP_%=;\n\t"                                           \
            "WAIT_DONE_%=:\n\t}"                                                  \
            :: "r"(_mbar), "r"(_parity) : "memory");                              \
    }                                                                             \
} while (0)

// ------------------------- fused conversion kernel -------------------------
__global__ void k_prep(const float* __restrict__ x, const float* __restrict__ w,
                       const float* __restrict__ sc) {
    if (blockIdx.x < XBLOCKS) {
        const int id = blockIdx.x * 256 + threadIdx.x;     // 16B output chunks (4,194,304)
        const int c  = id & 7;
        const int r  = (id >> 3) & 127;
        const int s  = (id >> 10) & 63;
        const int bm = id >> 16;
        const size_t m = (size_t)bm * 128 + r;
        const size_t k = (size_t)s * 64 + c * 8;

        const float4* src = reinterpret_cast<const float4*>(x + m * KDIM + k);
        float4 v0 = src[0], v1 = src[1];
        __half2 h0 = __floats2half2_rn(v0.x, v0.y);
        __half2 h1 = __floats2half2_rn(v0.z, v0.w);
        __half2 h2 = __floats2half2_rn(v1.x, v1.y);
        __half2 h3 = __floats2half2_rn(v1.z, v1.w);
        uint4 u;
        u.x = *reinterpret_cast<uint32_t*>(&h0);
        u.y = *reinterpret_cast<uint32_t*>(&h1);
        u.z = *reinterpret_cast<uint32_t*>(&h2);
        u.w = *reinterpret_cast<uint32_t*>(&h3);

        const size_t off = (((size_t)(bm * 64 + s) * 128 + r) << 7)
                         + (size_t)((c * 16) ^ ((r & 7) << 4));
        *reinterpret_cast<uint4*>(reinterpret_cast<char*>(g_Xh) + off) = u;
    } else {
        const int id = (blockIdx.x - XBLOCKS) * 256 + threadIdx.x;   // 2,097,152 chunks
        const int c  = id & 7;
        const int r  = (id >> 3) & 127;
        const int s  = (id >> 10) & 63;
        const int bn = id >> 16;                           // 0..31
        const size_t o = (size_t)bn * 128 + r;
        const size_t k = (size_t)s * 64 + c * 8;

        const float sv = fmaxf(sc[o * 32 + (s >> 1)], 1e-8f);   // 128-k scale group = 2 stages
        const __half hp = __float2half_rn(sv);
        const __half hn = __hneg(hp);

        const float4* src = reinterpret_cast<const float4*>(w + o * KDIM + k);
        float4 v0 = src[0], v1 = src[1];
        __half2 h0 = __halves2half2((v0.x >= 0.f) ? hp : hn, (v0.y >= 0.f) ? hp : hn);
        __half2 h1 = __halves2half2((v0.z >= 0.f) ? hp : hn, (v0.w >= 0.f) ? hp : hn);
        __half2 h2 = __halves2half2((v1.x >= 0.f) ? hp : hn, (v1.y >= 0.f) ? hp : hn);
        __half2 h3 = __halves2half2((v1.z >= 0.f) ? hp : hn, (v1.w >= 0.f) ? hp : hn);
        uint4 u;
        u.x = *reinterpret_cast<uint32_t*>(&h0);
        u.y = *reinterpret_cast<uint32_t*>(&h1);
        u.z = *reinterpret_cast<uint32_t*>(&h2);
        u.w = *reinterpret_cast<uint32_t*>(&h3);

        const size_t off = (((size_t)(bn * 64 + s) * 128 + r) << 7)
                         + (size_t)((c * 16) ^ ((r & 7) << 4));
        *reinterpret_cast<uint4*>(reinterpret_cast<char*>(g_Wh) + off) = u;
    }
}

// ------------------------- GEMM kernel -------------------------
// CTA 128x128, 128 threads, 4 warps 2(M) x 2(N), warp tile 64x64, 2 CTAs/SM.
// mbarrier ring with software-pipelined (non-blocking) waits: probes issued
// mid-stage, consumed later; next-stage ks0 fragments prefetched during ks3.
__global__ void __launch_bounds__(NTHREADS, 2) k_gemm(float* __restrict__ out) {
    extern __shared__ char smem[];
    const uint32_t sb = smem_u32(smem);
    const int tid = threadIdx.x;
    const int wid = tid >> 5;
    const int lane = tid & 31;

    const uint32_t mbF = sb + NSTAGE * STAGE_BYTES;      // full[0..2], 8B each
    const uint32_t mbE = mbF + 24;                       // empty[0..2]

    if (tid == 0) {
        #pragma unroll
        for (int i = 0; i < NSTAGE; ++i) {
            MBAR_INIT(mbF + i * 8, 128);                 // 128 cp.async noinc arrivals
            MBAR_INIT(mbE + i * 8, 4);                   // 4 warp arrivals
        }
    }
    __syncthreads();
    if (lane == 0) {                                     // pre-arm empties (phase 0)
        MBAR_ARRIVE(mbE + 0);
        MBAR_ARRIVE(mbE + 8);
        MBAR_ARRIVE(mbE + 16);
    }

    const int bm = blockIdx.x >> 5;              // 64 M tiles; N-fast: W stays L2-resident
    const int bn = blockIdx.x & 31;              // 32 N tiles
    const int wm = wid >> 1;                     // 0..1 (64 rows)
    const int wn = wid & 1;                      // 0..1 (64 cols)

    const char* gA = reinterpret_cast<const char*>(g_Xh) + (size_t)bm * 64 * A_BYTES;
    const char* gB = reinterpret_cast<const char*>(g_Wh) + (size_t)bn * 64 * B_BYTES;

    int pb = 0, pp = 0;                          // producer cursor (buffer, phase)
    auto produce_nw = [&](int s) {               // no empty-wait (caller guarantees)
        const uint32_t base = sb + (uint32_t)pb * STAGE_BYTES;
        const char* srcA = gA + (size_t)s * A_BYTES;
        const char* srcB = gB + (size_t)s * B_BYTES;
        #pragma unroll
        for (int i = 0; i < 8; ++i) {
            uint32_t off = (uint32_t)(tid + i * NTHREADS) * 16u;
            asm volatile("cp.async.cg.shared.global [%0], [%1], 16;"
                         :: "r"(base + off), "l"(srcA + off) : "memory");
        }
        #pragma unroll
        for (int i = 0; i < 8; ++i) {
            uint32_t off = (uint32_t)(tid + i * NTHREADS) * 16u;
            asm volatile("cp.async.cg.shared.global [%0], [%1], 16;"
                         :: "r"(base + A_BYTES + off), "l"(srcB + off) : "memory");
        }
        CPASYNC_MBAR_ARRIVE(mbF + pb * 8);
        if (++pb == NSTAGE) { pb = 0; pp ^= 1; }
    };

    // Fragment addressing (byte offsets within a stage image; rows stride 128B)
    uint32_t a_row[4], a_swz[4];
    uint32_t b_row[4], b_swz[4];
    const uint32_t a_kl = (uint32_t)((lane >> 4) << 4);
    const uint32_t b_kl = (uint32_t)(((lane >> 3) & 1) << 4);
    #pragma unroll
    for (int mt = 0; mt < 4; ++mt) {
        int row = wm * 64 + mt * 16 + (lane & 15);
        a_row[mt] = (uint32_t)row * 128u;
        a_swz[mt] = (uint32_t)((row & 7) << 4);
    }
    #pragma unroll
    for (int nt = 0; nt < 4; ++nt) {
        int row = wn * 64 + nt * 16 + (lane & 7) + ((lane >> 4) << 3);
        b_row[nt] = (uint32_t)row * 128u;
        b_swz[nt] = (uint32_t)((row & 7) << 4);
    }

    uint32_t a[2][4][4], b[2][4][4];

    auto ldfrag = [&](uint32_t base, int ks, int buf) {
        const uint32_t kk = (uint32_t)(ks * 32);
        const uint32_t bbase = base + A_BYTES;
        #pragma unroll
        for (int mt = 0; mt < 4; ++mt) {
            uint32_t ad = base + a_row[mt] + ((kk + a_kl) ^ a_swz[mt]);
            LDMATRIX_X4(a[buf][mt][0], a[buf][mt][1], a[buf][mt][2], a[buf][mt][3], ad);
        }
        #pragma unroll
        for (int nt = 0; nt < 4; ++nt) {
            uint32_t bd = bbase + b_row[nt] + ((kk + b_kl) ^ b_swz[nt]);
            LDMATRIX_X4(b[buf][nt][0], b[buf][nt][1], b[buf][nt][2], b[buf][nt][3], bd);
        }
    };

    // prologue: fill 2 stages (empties pre-armed -> waits pass immediately)
    MBAR_WAIT(mbE + 0, 0);
    produce_nw(0);
    MBAR_WAIT(mbE + 8, 0);
    produce_nw(1);

    float acc[4][8][4];
    #pragma unroll
    for (int i = 0; i < 4; ++i)
        #pragma unroll
        for (int j = 0; j < 8; ++j)
            #pragma unroll
            for (int k = 0; k < 4; ++k) acc[i][j][k] = 0.f;

    int cb = 0, cph = 0;                         // consumer cursor
    MBAR_WAIT(mbF + 0, 0);                       // stage 0 ready (blocking)
    ldfrag(sb, 0, 0);
    uint32_t pref = 1;

    #pragma unroll 1
    for (int t = 0; t < KSTAGES; ++t) {
        const uint32_t abase = sb + (uint32_t)cb * STAGE_BYTES;
        if (!pref) {                             // fallback: probe failed last stage
            MBAR_WAIT(mbF + cb * 8, cph);
            ldfrag(abase, 0, 0);
        }
        const int ncb = (cb + 1 == NSTAGE) ? 0 : cb + 1;
        const int nph = (cb + 1 == NSTAGE) ? (cph ^ 1) : cph;
        const uint32_t nbase = sb + (uint32_t)ncb * STAGE_BYTES;
        uint32_t tryE = 0, nextF = 0;

        #pragma unroll
        for (int ks = 0; ks < 4; ++ks) {
            const int cur = ks & 1;
            if (ks < 3) ldfrag(abase, ks + 1, cur ^ 1);
            if (ks == 1 && t + 2 < KSTAGES)
                MBAR_TRY(tryE, mbE + pb * 8, pp);        // probe; latency hides under MMAs
            if (ks == 2) {
                if (t + 2 < KSTAGES) {
                    if (!tryE) MBAR_WAIT(mbE + pb * 8, pp);
                    produce_nw(t + 2);
                }
                if (t + 1 < KSTAGES)
                    MBAR_TRY(nextF, mbF + ncb * 8, nph); // probe next stage's data
            }
            if (ks == 3 && nextF)
                ldfrag(nbase, 0, 0);                     // prefetch across stage boundary

            #pragma unroll
            for (int mt = 0; mt < 4; ++mt) {
                #pragma unroll
                for (int nt = 0; nt < 4; ++nt) {
                    MMA16816(acc[mt][2 * nt],     a[cur][mt][0], a[cur][mt][1], a[cur][mt][2], a[cur][mt][3],
                             b[cur][nt][0], b[cur][nt][1]);
                    MMA16816(acc[mt][2 * nt + 1], a[cur][mt][0], a[cur][mt][1], a[cur][mt][2], a[cur][mt][3],
                             b[cur][nt][2], b[cur][nt][3]);
                }
            }
        }

        __syncwarp();
        if (lane == 0) MBAR_ARRIVE(mbE + cb * 8);        // release buffer cb
        cb = ncb; cph = nph;
        pref = nextF;
    }

    // Epilogue: direct gmem stores
    {
        const size_t m0 = (size_t)bm * TM;
        const size_t n0 = (size_t)bn * TN;
        const int g = lane >> 2;
        const int tg = lane & 3;
        #pragma unroll
        for (int mt = 0; mt < 4; ++mt) {
            const size_t m = m0 + (size_t)(wm * 64 + mt * 16 + g);
            float* r0 = out + m * NDIM + n0 + wn * 64 + tg * 2;
            float* r1 = r0 + 8 * NDIM;
            #pragma unroll
            for (int j = 0; j < 8; ++j) {
                *reinterpret_cast<float2*>(r0 + j * 8) = make_float2(acc[mt][j][0], acc[mt][j][1]);
                *reinterpret_cast<float2*>(r1 + j * 8) = make_float2(acc[mt][j][2], acc[mt][j][3]);
            }
        }
    }
}

// ------------------------- launch -------------------------
extern "C" void kernel_launch(void* const* d_in, const int* in_sizes, int n_in,
                              void* d_out, int out_size) {
    const float* x = nullptr;
    const float* w = nullptr;
    const float* sc = nullptr;
    for (int i = 0; i < n_in; ++i) {
        if (in_sizes[i] == MDIM * KDIM) x = (const float*)d_in[i];
        else if (in_sizes[i] == NDIM * KDIM) w = (const float*)d_in[i];
        else if (in_sizes[i] == NDIM * (KDIM / 128)) sc = (const float*)d_in[i];
    }
    float* out = (float*)d_out;

    cudaFuncSetAttribute(k_gemm, cudaFuncAttributeMaxDynamicSharedMemorySize, SMEM_BYTES);

    k_prep<<<XBLOCKS + WBLOCKS, 256>>>(x, w, sc);
    k_gemm<<<(MDIM / TM) * (NDIM / TN), NTHREADS, SMEM_BYTES>>>(out);
}

// round 14
// speedup vs baseline: 1.0038x; 1.0038x over previous
#include <cuda_runtime.h>
#include <cuda_fp16.h>
#include <cstdint>

// out[M,N] = X[M,K] @ Wq[N,K]^T, Wq = sign(W)*max(scales,1e-8), groups of 128 along K
#define MDIM 8192
#define NDIM 4096
#define KDIM 4096

#define TM 128
#define TN 128
#define TKH 64                       // halves per K stage (one 128B panel per row)
#define NSTAGE 3
#define KSTAGES (KDIM / TKH)         // 64

#define A_BYTES (TM * 128)           // 16384 per stage
#define B_BYTES (TN * 128)           // 16384 per stage
#define STAGE_BYTES (A_BYTES + B_BYTES)        // 32768
#define SMEM_BYTES (NSTAGE * STAGE_BYTES + 64) // 98368 -> 2 CTAs/SM

#define NTHREADS 128

#define XBLOCKS (MDIM * KDIM * 2 / 16 / 256)   // 16384
#define WBLOCKS (NDIM * KDIM * 2 / 16 / 256)   // 8192

// Pre-swizzled tile-major operand images (exact smem byte image per (tile,stage)).
__device__ __align__(16) __half g_Xh[(size_t)MDIM * KDIM];   // 64 MB
__device__ __align__(16) __half g_Wh[(size_t)NDIM * KDIM];   // 32 MB

__device__ __forceinline__ uint32_t smem_u32(const void* p) {
    uint32_t a;
    asm("{ .reg .u64 t; cvta.to.shared.u64 t, %1; cvt.u32.u64 %0, t; }" : "=r"(a) : "l"(p));
    return a;
}

#define LDMATRIX_X4(r0, r1, r2, r3, addr)                                        \
    asm volatile("ldmatrix.sync.aligned.m8n8.x4.shared.b16 {%0,%1,%2,%3}, [%4];" \
                 : "=r"(r0), "=r"(r1), "=r"(r2), "=r"(r3) : "r"(addr))

#define MMA16816(c, a0, a1, a2, a3, b0, b1)                                      \
    asm volatile("mma.sync.aligned.m16n8k16.row.col.f32.f16.f16.f32 "            \
                 "{%0,%1,%2,%3}, {%4,%5,%6,%7}, {%8,%9}, {%0,%1,%2,%3};"         \
                 : "+f"((c)[0]), "+f"((c)[1]), "+f"((c)[2]), "+f"((c)[3])        \
                 : "r"(a0), "r"(a1), "r"(a2), "r"(a3), "r"(b0), "r"(b1))

#define MBAR_INIT(addr, cnt) \
    asm volatile("mbarrier.init.shared.b64 [%0], %1;" :: "r"(addr), "r"(cnt) : "memory")

#define MBAR_ARRIVE(addr) \
    asm volatile("mbarrier.arrive.shared.b64 _, [%0];" :: "r"(addr) : "memory")

#define CPASYNC_MBAR_ARRIVE(addr) \
    asm volatile("cp.async.mbarrier.arrive.noinc.shared.b64 [%0];" :: "r"(addr) : "memory")

// Non-blocking probe: result flag only (latency overlaps MMA issue).
#define MBAR_TRY(res, addr, parity)                                               \
    asm volatile(                                                                 \
        "{\n\t.reg .pred p;\n\t"                                                  \
        "mbarrier.try_wait.parity.acquire.cta.shared::cta.b64 p, [%1], %2;\n\t"  \
        "selp.b32 %0, 1, 0, p;\n\t}"                                              \
        : "=r"(res) : "r"((uint32_t)(addr)), "r"((uint32_t)(parity)) : "memory")

#define MBAR_WAIT(mbar_addr, phase_parity) do {                                   \
    uint32_t _mbar = (uint32_t)(mbar_addr);                                       \
    uint32_t _parity = (uint32_t)(phase_parity);                                  \
    uint32_t _done;                                                               \
    asm volatile(                                                                 \
        "{\n\t.reg .pred p;\n\t"                                                  \
        "mbarrier.try_wait.parity.acquire.cta.shared::cta.b64 p, [%1], %2;\n\t"  \
        "selp.b32 %0, 1, 0, p;\n\t}"                                              \
        : "=r"(_done) : "r"(_mbar), "r"(_parity) : "memory");                     \
    if (!_done) {                                                                 \
        asm volatile(                                                             \
            "{\n\t.reg .pred P1;\n\t"                                             \
            "WAIT_LOOP_%=:\n\t"                                                   \
            "mbarrier.try_wait.parity.acquire.cta.shared::cta.b64 P1, [%0], %1, 0x989680;\n\t" \
            "@P1 bra.uni WAIT_DONE_%=;\n\t"                                       \
            "bra.uni WAIT_LOOP_%=;\n\t"                                           \
            "WAIT_DONE_%=:\n\t}"                                                  \
            :: "r"(_mbar), "r"(_parity) : "memory");                              \
    }                                                                             \
} while (0)

// ------------------------- fused conversion kernel -------------------------
__global__ void k_prep(const float* __restrict__ x, const float* __restrict__ w,
                       const float* __restrict__ sc) {
    if (blockIdx.x < XBLOCKS) {
        const int id = blockIdx.x * 256 + threadIdx.x;     // 16B output chunks (4,194,304)
        const int c  = id & 7;
        const int r  = (id >> 3) & 127;
        const int s  = (id >> 10) & 63;
        const int bm = id >> 16;
        const size_t m = (size_t)bm * 128 + r;
        const size_t k = (size_t)s * 64 + c * 8;

        const float4* src = reinterpret_cast<const float4*>(x + m * KDIM + k);
        float4 v0 = src[0], v1 = src[1];
        __half2 h0 = __floats2half2_rn(v0.x, v0.y);
        __half2 h1 = __floats2half2_rn(v0.z, v0.w);
        __half2 h2 = __floats2half2_rn(v1.x, v1.y);
        __half2 h3 = __floats2half2_rn(v1.z, v1.w);
        uint4 u;
        u.x = *reinterpret_cast<uint32_t*>(&h0);
        u.y = *reinterpret_cast<uint32_t*>(&h1);
        u.z = *reinterpret_cast<uint32_t*>(&h2);
        u.w = *reinterpret_cast<uint32_t*>(&h3);

        const size_t off = (((size_t)(bm * 64 + s) * 128 + r) << 7)
                         + (size_t)((c * 16) ^ ((r & 7) << 4));
        *reinterpret_cast<uint4*>(reinterpret_cast<char*>(g_Xh) + off) = u;
    } else {
        const int id = (blockIdx.x - XBLOCKS) * 256 + threadIdx.x;   // 2,097,152 chunks
        const int c  = id & 7;
        const int r  = (id >> 3) & 127;
        const int s  = (id >> 10) & 63;
        const int bn = id >> 16;                           // 0..31
        const size_t o = (size_t)bn * 128 + r;
        const size_t k = (size_t)s * 64 + c * 8;

        const float sv = fmaxf(sc[o * 32 + (s >> 1)], 1e-8f);   // 128-k scale group = 2 stages
        const __half hp = __float2half_rn(sv);
        const __half hn = __hneg(hp);

        const float4* src = reinterpret_cast<const float4*>(w + o * KDIM + k);
        float4 v0 = src[0], v1 = src[1];
        __half2 h0 = __halves2half2((v0.x >= 0.f) ? hp : hn, (v0.y >= 0.f) ? hp : hn);
        __half2 h1 = __halves2half2((v0.z >= 0.f) ? hp : hn, (v0.w >= 0.f) ? hp : hn);
        __half2 h2 = __halves2half2((v1.x >= 0.f) ? hp : hn, (v1.y >= 0.f) ? hp : hn);
        __half2 h3 = __halves2half2((v1.z >= 0.f) ? hp : hn, (v1.w >= 0.f) ? hp : hn);
        uint4 u;
        u.x = *reinterpret_cast<uint32_t*>(&h0);
        u.y = *reinterpret_cast<uint32_t*>(&h1);
        u.z = *reinterpret_cast<uint32_t*>(&h2);
        u.w = *reinterpret_cast<uint32_t*>(&h3);

        const size_t off = (((size_t)(bn * 64 + s) * 128 + r) << 7)
                         + (size_t)((c * 16) ^ ((r & 7) << 4));
        *reinterpret_cast<uint4*>(reinterpret_cast<char*>(g_Wh) + off) = u;
    }
}

// ------------------------- GEMM kernel -------------------------
// CTA 128x128, 128 threads, 4 warps 2(M) x 2(N), warp tile 64x64, 2 CTAs/SM.
// R12 structure + ONE next-stage full probe (ks=2) feeding a cross-boundary
// fragment prefetch (ks=3). Producer empty-wait stays blocking (never binding).
__global__ void __launch_bounds__(NTHREADS, 2) k_gemm(float* __restrict__ out) {
    extern __shared__ char smem[];
    const uint32_t sb = smem_u32(smem);
    const int tid = threadIdx.x;
    const int wid = tid >> 5;
    const int lane = tid & 31;

    const uint32_t mbF = sb + NSTAGE * STAGE_BYTES;      // full[0..2], 8B each
    const uint32_t mbE = mbF + 24;                       // empty[0..2]

    if (tid == 0) {
        #pragma unroll
        for (int i = 0; i < NSTAGE; ++i) {
            MBAR_INIT(mbF + i * 8, 128);                 // 128 cp.async noinc arrivals
            MBAR_INIT(mbE + i * 8, 4);                   // 4 warp arrivals
        }
    }
    __syncthreads();
    if (lane == 0) {                                     // pre-arm empties (phase 0)
        MBAR_ARRIVE(mbE + 0);
        MBAR_ARRIVE(mbE + 8);
        MBAR_ARRIVE(mbE + 16);
    }

    const int bm = blockIdx.x >> 5;              // 64 M tiles; N-fast: W stays L2-resident
    const int bn = blockIdx.x & 31;              // 32 N tiles
    const int wm = wid >> 1;                     // 0..1 (64 rows)
    const int wn = wid & 1;                      // 0..1 (64 cols)

    const char* gA = reinterpret_cast<const char*>(g_Xh) + (size_t)bm * 64 * A_BYTES;
    const char* gB = reinterpret_cast<const char*>(g_Wh) + (size_t)bn * 64 * B_BYTES;

    int pb = 0, pp = 0;                          // producer cursor (buffer, phase)
    auto produce = [&](int s) {
        MBAR_WAIT(mbE + pb * 8, pp);             // buffer free (all warps released it)
        const uint32_t base = sb + (uint32_t)pb * STAGE_BYTES;
        const char* srcA = gA + (size_t)s * A_BYTES;
        const char* srcB = gB + (size_t)s * B_BYTES;
        #pragma unroll
        for (int i = 0; i < 8; ++i) {
            uint32_t off = (uint32_t)(tid + i * NTHREADS) * 16u;
            asm volatile("cp.async.cg.shared.global [%0], [%1], 16;"
                         :: "r"(base + off), "l"(srcA + off) : "memory");
        }
        #pragma unroll
        for (int i = 0; i < 8; ++i) {
            uint32_t off = (uint32_t)(tid + i * NTHREADS) * 16u;
            asm volatile("cp.async.cg.shared.global [%0], [%1], 16;"
                         :: "r"(base + A_BYTES + off), "l"(srcB + off) : "memory");
        }
        CPASYNC_MBAR_ARRIVE(mbF + pb * 8);       // arrive when this thread's copies land
        if (++pb == NSTAGE) { pb = 0; pp ^= 1; }
    };

    // Fragment addressing (byte offsets within a stage image; rows stride 128B)
    uint32_t a_row[4], a_swz[4];
    uint32_t b_row[4], b_swz[4];
    const uint32_t a_kl = (uint32_t)((lane >> 4) << 4);
    const uint32_t b_kl = (uint32_t)(((lane >> 3) & 1) << 4);
    #pragma unroll
    for (int mt = 0; mt < 4; ++mt) {
        int row = wm * 64 + mt * 16 + (lane & 15);
        a_row[mt] = (uint32_t)row * 128u;
        a_swz[mt] = (uint32_t)((row & 7) << 4);
    }
    #pragma unroll
    for (int nt = 0; nt < 4; ++nt) {
        int row = wn * 64 + nt * 16 + (lane & 7) + ((lane >> 4) << 3);
        b_row[nt] = (uint32_t)row * 128u;
        b_swz[nt] = (uint32_t)((row & 7) << 4);
    }

    uint32_t a[2][4][4], b[2][4][4];

    auto ldfrag = [&](uint32_t base, int ks, int buf) {
        const uint32_t kk = (uint32_t)(ks * 32);
        const uint32_t bbase = base + A_BYTES;
        #pragma unroll
        for (int mt = 0; mt < 4; ++mt) {
            uint32_t ad = base + a_row[mt] + ((kk + a_kl) ^ a_swz[mt]);
            LDMATRIX_X4(a[buf][mt][0], a[buf][mt][1], a[buf][mt][2], a[buf][mt][3], ad);
        }
        #pragma unroll
        for (int nt = 0; nt < 4; ++nt) {
            uint32_t bd = bbase + b_row[nt] + ((kk + b_kl) ^ b_swz[nt]);
            LDMATRIX_X4(b[buf][nt][0], b[buf][nt][1], b[buf][nt][2], b[buf][nt][3], bd);
        }
    };

    produce(0);
    produce(1);

    float acc[4][8][4];
    #pragma unroll
    for (int i = 0; i < 4; ++i)
        #pragma unroll
        for (int j = 0; j < 8; ++j)
            #pragma unroll
            for (int k = 0; k < 4; ++k) acc[i][j][k] = 0.f;

    int cb = 0, cph = 0;                         // consumer cursor
    MBAR_WAIT(mbF + 0, 0);                       // stage 0 ready
    ldfrag(sb, 0, 0);
    uint32_t pref = 1;

    #pragma unroll 1
    for (int t = 0; t < KSTAGES; ++t) {
        if (t + 2 < KSTAGES) produce(t + 2);     // empty-wait passes (freed at end of t-1)

        const uint32_t abase = sb + (uint32_t)cb * STAGE_BYTES;
        if (!pref) {                             // slow path: prefetch missed last stage
            MBAR_WAIT(mbF + cb * 8, cph);
            ldfrag(abase, 0, 0);
        }
        const int ncb = (cb + 1 == NSTAGE) ? 0 : cb + 1;
        const int nph = (cb + 1 == NSTAGE) ? (cph ^ 1) : cph;
        const uint32_t nbase = sb + (uint32_t)ncb * STAGE_BYTES;
        uint32_t nextF = 0;

        #pragma unroll
        for (int ks = 0; ks < 4; ++ks) {
            const int cur = ks & 1;
            if (ks < 3) ldfrag(abase, ks + 1, cur ^ 1);
            if (ks == 2 && t + 1 < KSTAGES)
                MBAR_TRY(nextF, mbF + ncb * 8, nph);     // probe next stage's data
            if (ks == 3 && nextF)
                ldfrag(nbase, 0, 0);                     // cross-boundary prefetch

            #pragma unroll
            for (int mt = 0; mt < 4; ++mt) {
                #pragma unroll
                for (int nt = 0; nt < 4; ++nt) {
                    MMA16816(acc[mt][2 * nt],     a[cur][mt][0], a[cur][mt][1], a[cur][mt][2], a[cur][mt][3],
                             b[cur][nt][0], b[cur][nt][1]);
                    MMA16816(acc[mt][2 * nt + 1], a[cur][mt][0], a[cur][mt][1], a[cur][mt][2], a[cur][mt][3],
                             b[cur][nt][2], b[cur][nt][3]);
                }
            }
        }

        __syncwarp();
        if (lane == 0) MBAR_ARRIVE(mbE + cb * 8);        // release buffer cb
        cb = ncb; cph = nph;
        pref = nextF;
    }

    // Epilogue: direct gmem stores
    {
        const size_t m0 = (size_t)bm * TM;
        const size_t n0 = (size_t)bn * TN;
        const int g = lane >> 2;
        const int tg = lane & 3;
        #pragma unroll
        for (int mt = 0; mt < 4; ++mt) {
            const size_t m = m0 + (size_t)(wm * 64 + mt * 16 + g);
            float* r0 = out + m * NDIM + n0 + wn * 64 + tg * 2;
            float* r1 = r0 + 8 * NDIM;
            #pragma unroll
            for (int j = 0; j < 8; ++j) {
                *reinterpret_cast<float2*>(r0 + j * 8) = make_float2(acc[mt][j][0], acc[mt][j][1]);
                *reinterpret_cast<float2*>(r1 + j * 8) = make_float2(acc[mt][j][2], acc[mt][j][3]);
            }
        }
    }
}

// ------------------------- launch -------------------------
extern "C" void kernel_launch(void* const* d_in, const int* in_sizes, int n_in,
                              void* d_out, int out_size) {
    const float* x = nullptr;
    const float* w = nullptr;
    const float* sc = nullptr;
    for (int i = 0; i < n_in; ++i) {
        if (in_sizes[i] == MDIM * KDIM) x = (const float*)d_in[i];
        else if (in_sizes[i] == NDIM * KDIM) w = (const float*)d_in[i];
        else if (in_sizes[i] == NDIM * (KDIM / 128)) sc = (const float*)d_in[i];
    }
    float* out = (float*)d_out;

    cudaFuncSetAttribute(k_gemm, cudaFuncAttributeMaxDynamicSharedMemorySize, SMEM_BYTES);

    k_prep<<<XBLOCKS + WBLOCKS, 256>>>(x, w, sc);
    k_gemm<<<(MDIM / TM) * (NDIM / TN), NTHREADS, SMEM_BYTES>>>(out);
}

// round 15
// speedup vs baseline: 1.0175x; 1.0137x over previous
#include <cuda_runtime.h>
#include <cuda_fp16.h>
#include <cstdint>

// out[M,N] = X[M,K] @ Wq[N,K]^T, Wq = sign(W)*max(scales,1e-8), groups of 128 along K
#define MDIM 8192
#define NDIM 4096
#define KDIM 4096

#define TM 128
#define TN 128
#define TKH 64                       // halves per K stage (one 128B panel per row)
#define NSTAGE 3
#define KSTAGES (KDIM / TKH)         // 64

#define A_BYTES (TM * 128)           // 16384 per stage
#define B_BYTES (TN * 128)           // 16384 per stage
#define STAGE_BYTES (A_BYTES + B_BYTES)        // 32768
#define SMEM_BYTES (NSTAGE * STAGE_BYTES + 64) // 98368 -> 2 CTAs/SM

#define NTHREADS 128

#define XBLOCKS2 (MDIM * KDIM * 2 / 16 / 256 / 2)   // 8192 (2 chunks/thread)
#define WBLOCKS2 (NDIM * KDIM * 2 / 16 / 256 / 2)   // 4096

// Pre-swizzled tile-major operand images (exact smem byte image per (tile,stage)).
__device__ __align__(16) __half g_Xh[(size_t)MDIM * KDIM];   // 64 MB
__device__ __align__(16) __half g_Wh[(size_t)NDIM * KDIM];   // 32 MB

__device__ __forceinline__ uint32_t smem_u32(const void* p) {
    uint32_t a;
    asm("{ .reg .u64 t; cvta.to.shared.u64 t, %1; cvt.u32.u64 %0, t; }" : "=r"(a) : "l"(p));
    return a;
}

#define LDMATRIX_X4(r0, r1, r2, r3, addr)                                        \
    asm volatile("ldmatrix.sync.aligned.m8n8.x4.shared.b16 {%0,%1,%2,%3}, [%4];" \
                 : "=r"(r0), "=r"(r1), "=r"(r2), "=r"(r3) : "r"(addr))

#define MMA16816(c, a0, a1, a2, a3, b0, b1)                                      \
    asm volatile("mma.sync.aligned.m16n8k16.row.col.f32.f16.f16.f32 "            \
                 "{%0,%1,%2,%3}, {%4,%5,%6,%7}, {%8,%9}, {%0,%1,%2,%3};"         \
                 : "+f"((c)[0]), "+f"((c)[1]), "+f"((c)[2]), "+f"((c)[3])        \
                 : "r"(a0), "r"(a1), "r"(a2), "r"(a3), "r"(b0), "r"(b1))

#define MBAR_INIT(addr, cnt) \
    asm volatile("mbarrier.init.shared.b64 [%0], %1;" :: "r"(addr), "r"(cnt) : "memory")

#define MBAR_ARRIVE(addr) \
    asm volatile("mbarrier.arrive.shared.b64 _, [%0];" :: "r"(addr) : "memory")

#define CPASYNC_MBAR_ARRIVE(addr) \
    asm volatile("cp.async.mbarrier.arrive.noinc.shared.b64 [%0];" :: "r"(addr) : "memory")

// Non-blocking probe: result flag only (latency overlaps MMA issue).
#define MBAR_TRY(res, addr, parity)                                               \
    asm volatile(                                                                 \
        "{\n\t.reg .pred p;\n\t"                                                  \
        "mbarrier.try_wait.parity.acquire.cta.shared::cta.b64 p, [%1], %2;\n\t"  \
        "selp.b32 %0, 1, 0, p;\n\t}"                                              \
        : "=r"(res) : "r"((uint32_t)(addr)), "r"((uint32_t)(parity)) : "memory")

#define MBAR_WAIT(mbar_addr, phase_parity) do {                                   \
    uint32_t _mbar = (uint32_t)(mbar_addr);                                       \
    uint32_t _parity = (uint32_t)(phase_parity);                                  \
    uint32_t _done;                                                               \
    asm volatile(                                                                 \
        "{\n\t.reg .pred p;\n\t"                                                  \
        "mbarrier.try_wait.parity.acquire.cta.shared::cta.b64 p, [%1], %2;\n\t"  \
        "selp.b32 %0, 1, 0, p;\n\t}"                                              \
        : "=r"(_done) : "r"(_mbar), "r"(_parity) : "memory");                     \
    if (!_done) {                                                                 \
        asm volatile(                                                             \
            "{\n\t.reg .pred P1;\n\t"                                             \
            "WAIT_LOOP_%=:\n\t"                                                   \
            "mbarrier.try_wait.parity.acquire.cta.shared::cta.b64 P1, [%0], %1, 0x989680;\n\t" \
            "@P1 bra.uni WAIT_DONE_%=;\n\t"                                       \
            "bra.uni WAIT_LOOP_%=;\n\t"                                           \
            "WAIT_DONE_%=:\n\t}"                                                  \
            :: "r"(_mbar), "r"(_parity) : "memory");                              \
    }                                                                             \
} while (0)

// ------------------------- fused conversion kernel -------------------------
// 2 chunks per thread: loads batched first (MLP=4), then converts/stores.
__global__ void k_prep(const float* __restrict__ x, const float* __restrict__ w,
                       const float* __restrict__ sc) {
    if (blockIdx.x < XBLOCKS2) {
        const int id0 = (blockIdx.x * 256 + threadIdx.x) * 2;
        #pragma unroll
        for (int q = 0; q < 2; ++q) {
            const int id = id0 + q;
            const int c  = id & 7;
            const int r  = (id >> 3) & 127;
            const int s  = (id >> 10) & 63;
            const int bm = id >> 16;
            const size_t m = (size_t)bm * 128 + r;
            const size_t k = (size_t)s * 64 + c * 8;

            const float4* src = reinterpret_cast<const float4*>(x + m * KDIM + k);
            float4 v0 = src[0], v1 = src[1];
            __half2 h0 = __floats2half2_rn(v0.x, v0.y);
            __half2 h1 = __floats2half2_rn(v0.z, v0.w);
            __half2 h2 = __floats2half2_rn(v1.x, v1.y);
            __half2 h3 = __floats2half2_rn(v1.z, v1.w);
            uint4 u;
            u.x = *reinterpret_cast<uint32_t*>(&h0);
            u.y = *reinterpret_cast<uint32_t*>(&h1);
            u.z = *reinterpret_cast<uint32_t*>(&h2);
            u.w = *reinterpret_cast<uint32_t*>(&h3);

            const size_t off = (((size_t)(bm * 64 + s) * 128 + r) << 7)
                             + (size_t)((c * 16) ^ ((r & 7) << 4));
            *reinterpret_cast<uint4*>(reinterpret_cast<char*>(g_Xh) + off) = u;
        }
    } else {
        const int id0 = ((blockIdx.x - XBLOCKS2) * 256 + threadIdx.x) * 2;
        #pragma unroll
        for (int q = 0; q < 2; ++q) {
            const int id = id0 + q;
            const int c  = id & 7;
            const int r  = (id >> 3) & 127;
            const int s  = (id >> 10) & 63;
            const int bn = id >> 16;                           // 0..31
            const size_t o = (size_t)bn * 128 + r;
            const size_t k = (size_t)s * 64 + c * 8;

            const float sv = fmaxf(sc[o * 32 + (s >> 1)], 1e-8f);  // 128-k scale group
            const __half hp = __float2half_rn(sv);
            const __half hn = __hneg(hp);

            const float4* src = reinterpret_cast<const float4*>(w + o * KDIM + k);
            float4 v0 = src[0], v1 = src[1];
            __half2 h0 = __halves2half2((v0.x >= 0.f) ? hp : hn, (v0.y >= 0.f) ? hp : hn);
            __half2 h1 = __halves2half2((v0.z >= 0.f) ? hp : hn, (v0.w >= 0.f) ? hp : hn);
            __half2 h2 = __halves2half2((v1.x >= 0.f) ? hp : hn, (v1.y >= 0.f) ? hp : hn);
            __half2 h3 = __halves2half2((v1.z >= 0.f) ? hp : hn, (v1.w >= 0.f) ? hp : hn);
            uint4 u;
            u.x = *reinterpret_cast<uint32_t*>(&h0);
            u.y = *reinterpret_cast<uint32_t*>(&h1);
            u.z = *reinterpret_cast<uint32_t*>(&h2);
            u.w = *reinterpret_cast<uint32_t*>(&h3);

            const size_t off = (((size_t)(bn * 64 + s) * 128 + r) << 7)
                             + (size_t)((c * 16) ^ ((r & 7) << 4));
            *reinterpret_cast<uint4*>(reinterpret_cast<char*>(g_Wh) + off) = u;
        }
    }
}

// ------------------------- GEMM kernel -------------------------
// CTA 128x128, 128 threads, 4 warps 2(M) x 2(N), warp tile 64x64, 2 CTAs/SM.
// R14 + early empty-release at ks=2 (all smem reads of the buffer complete,
// enforced by an XOR dependency chain over every live LDSM's output regs).
__global__ void __launch_bounds__(NTHREADS, 2) k_gemm(float* __restrict__ out) {
    extern __shared__ char smem[];
    const uint32_t sb = smem_u32(smem);
    const int tid = threadIdx.x;
    const int wid = tid >> 5;
    const int lane = tid & 31;

    const uint32_t mbF = sb + NSTAGE * STAGE_BYTES;      // full[0..2], 8B each
    const uint32_t mbE = mbF + 24;                       // empty[0..2]

    if (tid == 0) {
        #pragma unroll
        for (int i = 0; i < NSTAGE; ++i) {
            MBAR_INIT(mbF + i * 8, 128);                 // 128 cp.async noinc arrivals
            MBAR_INIT(mbE + i * 8, 4);                   // 4 warp arrivals
        }
    }
    __syncthreads();
    if (lane == 0) {                                     // pre-arm empties (phase 0)
        MBAR_ARRIVE(mbE + 0);
        MBAR_ARRIVE(mbE + 8);
        MBAR_ARRIVE(mbE + 16);
    }

    const int bm = blockIdx.x >> 5;              // 64 M tiles; N-fast: W stays L2-resident
    const int bn = blockIdx.x & 31;              // 32 N tiles
    const int wm = wid >> 1;                     // 0..1 (64 rows)
    const int wn = wid & 1;                      // 0..1 (64 cols)

    const char* gA = reinterpret_cast<const char*>(g_Xh) + (size_t)bm * 64 * A_BYTES;
    const char* gB = reinterpret_cast<const char*>(g_Wh) + (size_t)bn * 64 * B_BYTES;

    int pb = 0, pp = 0;                          // producer cursor (buffer, phase)
    auto produce = [&](int s) {
        MBAR_WAIT(mbE + pb * 8, pp);             // buffer free (all warps released it)
        const uint32_t base = sb + (uint32_t)pb * STAGE_BYTES;
        const char* srcA = gA + (size_t)s * A_BYTES;
        const char* srcB = gB + (size_t)s * B_BYTES;
        #pragma unroll
        for (int i = 0; i < 8; ++i) {
            uint32_t off = (uint32_t)(tid + i * NTHREADS) * 16u;
            asm volatile("cp.async.cg.shared.global [%0], [%1], 16;"
                         :: "r"(base + off), "l"(srcA + off) : "memory");
        }
        #pragma unroll
        for (int i = 0; i < 8; ++i) {
            uint32_t off = (uint32_t)(tid + i * NTHREADS) * 16u;
            asm volatile("cp.async.cg.shared.global [%0], [%1], 16;"
                         :: "r"(base + A_BYTES + off), "l"(srcB + off) : "memory");
        }
        CPASYNC_MBAR_ARRIVE(mbF + pb * 8);       // arrive when this thread's copies land
        if (++pb == NSTAGE) { pb = 0; pp ^= 1; }
    };

    // Fragment addressing (byte offsets within a stage image; rows stride 128B)
    uint32_t a_row[4], a_swz[4];
    uint32_t b_row[4], b_swz[4];
    const uint32_t a_kl = (uint32_t)((lane >> 4) << 4);
    const uint32_t b_kl = (uint32_t)(((lane >> 3) & 1) << 4);
    #pragma unroll
    for (int mt = 0; mt < 4; ++mt) {
        int row = wm * 64 + mt * 16 + (lane & 15);
        a_row[mt] = (uint32_t)row * 128u;
        a_swz[mt] = (uint32_t)((row & 7) << 4);
    }
    #pragma unroll
    for (int nt = 0; nt < 4; ++nt) {
        int row = wn * 64 + nt * 16 + (lane & 7) + ((lane >> 4) << 3);
        b_row[nt] = (uint32_t)row * 128u;
        b_swz[nt] = (uint32_t)((row & 7) << 4);
    }

    uint32_t a[2][4][4], b[2][4][4];

    auto ldfrag = [&](uint32_t base, int ks, int buf) {
        const uint32_t kk = (uint32_t)(ks * 32);
        const uint32_t bbase = base + A_BYTES;
        #pragma unroll
        for (int mt = 0; mt < 4; ++mt) {
            uint32_t ad = base + a_row[mt] + ((kk + a_kl) ^ a_swz[mt]);
            LDMATRIX_X4(a[buf][mt][0], a[buf][mt][1], a[buf][mt][2], a[buf][mt][3], ad);
        }
        #pragma unroll
        for (int nt = 0; nt < 4; ++nt) {
            uint32_t bd = bbase + b_row[nt] + ((kk + b_kl) ^ b_swz[nt]);
            LDMATRIX_X4(b[buf][nt][0], b[buf][nt][1], b[buf][nt][2], b[buf][nt][3], bd);
        }
    };

    produce(0);
    produce(1);

    float acc[4][8][4];
    #pragma unroll
    for (int i = 0; i < 4; ++i)
        #pragma unroll
        for (int j = 0; j < 8; ++j)
            #pragma unroll
            for (int k = 0; k < 4; ++k) acc[i][j][k] = 0.f;

    int cb = 0, cph = 0;                         // consumer cursor
    MBAR_WAIT(mbF + 0, 0);                       // stage 0 ready
    ldfrag(sb, 0, 0);
    uint32_t pref = 1;

    #pragma unroll 1
    for (int t = 0; t < KSTAGES; ++t) {
        if (t + 2 < KSTAGES) produce(t + 2);     // empty freed early at ks=2 of stage t-1

        const uint32_t abase = sb + (uint32_t)cb * STAGE_BYTES;
        if (!pref) {                             // slow path: prefetch missed last stage
            MBAR_WAIT(mbF + cb * 8, cph);
            ldfrag(abase, 0, 0);
        }
        const int ncb = (cb + 1 == NSTAGE) ? 0 : cb + 1;
        const int nph = (cb + 1 == NSTAGE) ? (cph ^ 1) : cph;
        const uint32_t nbase = sb + (uint32_t)ncb * STAGE_BYTES;
        uint32_t nextF = 0;

        #pragma unroll
        for (int ks = 0; ks < 4; ++ks) {
            const int cur = ks & 1;
            if (ks < 3) ldfrag(abase, ks + 1, cur ^ 1);
            if (ks == 2) {
                // All LDSM reads from abase now issued (frags 0..3). Force their
                // completion (SB waits via XOR chain over one reg per LDSM.x4 of
                // both live buffers), then release the buffer to the producer.
                uint32_t dep = a[0][0][0] ^ a[0][1][0] ^ a[0][2][0] ^ a[0][3][0]
                             ^ a[1][0][0] ^ a[1][1][0] ^ a[1][2][0] ^ a[1][3][0]
                             ^ b[0][0][0] ^ b[0][1][0] ^ b[0][2][0] ^ b[0][3][0]
                             ^ b[1][0][0] ^ b[1][1][0] ^ b[1][2][0] ^ b[1][3][0];
                asm volatile("" : "+r"(dep));    // keep chain live -> LDSM completion
                __syncwarp();
                if (lane == 0) MBAR_ARRIVE(mbE + cb * 8);
                if (t + 1 < KSTAGES)
                    MBAR_TRY(nextF, mbF + ncb * 8, nph);     // probe next stage's data
            }
            if (ks == 3 && nextF)
                ldfrag(nbase, 0, 0);                         // cross-boundary prefetch

            #pragma unroll
            for (int mt = 0; mt < 4; ++mt) {
                #pragma unroll
                for (int nt = 0; nt < 4; ++nt) {
                    MMA16816(acc[mt][2 * nt],     a[cur][mt][0], a[cur][mt][1], a[cur][mt][2], a[cur][mt][3],
                             b[cur][nt][0], b[cur][nt][1]);
                    MMA16816(acc[mt][2 * nt + 1], a[cur][mt][0], a[cur][mt][1], a[cur][mt][2], a[cur][mt][3],
                             b[cur][nt][2], b[cur][nt][3]);
                }
            }
        }

        cb = ncb; cph = nph;
        pref = nextF;
    }

    // Epilogue: direct gmem stores
    {
        const size_t m0 = (size_t)bm * TM;
        const size_t n0 = (size_t)bn * TN;
        const int g = lane >> 2;
        const int tg = lane & 3;
        #pragma unroll
        for (int mt = 0; mt < 4; ++mt) {
            const size_t m = m0 + (size_t)(wm * 64 + mt * 16 + g);
            float* r0 = out + m * NDIM + n0 + wn * 64 + tg * 2;
            float* r1 = r0 + 8 * NDIM;
            #pragma unroll
            for (int j = 0; j < 8; ++j) {
                *reinterpret_cast<float2*>(r0 + j * 8) = make_float2(acc[mt][j][0], acc[mt][j][1]);
                *reinterpret_cast<float2*>(r1 + j * 8) = make_float2(acc[mt][j][2], acc[mt][j][3]);
            }
        }
    }
}

// ------------------------- launch -------------------------
extern "C" void kernel_launch(void* const* d_in, const int* in_sizes, int n_in,
                              void* d_out, int out_size) {
    const float* x = nullptr;
    const float* w = nullptr;
    const float* sc = nullptr;
    for (int i = 0; i < n_in; ++i) {
        if (in_sizes[i] == MDIM * KDIM) x = (const float*)d_in[i];
        else if (in_sizes[i] == NDIM * KDIM) w = (const float*)d_in[i];
        else if (in_sizes[i] == NDIM * (KDIM / 128)) sc = (const float*)d_in[i];
    }
    float* out = (float*)d_out;

    cudaFuncSetAttribute(k_gemm, cudaFuncAttributeMaxDynamicSharedMemorySize, SMEM_BYTES);

    k_prep<<<XBLOCKS2 + WBLOCKS2, 256>>>(x, w, sc);
    k_gemm<<<(MDIM / TM) * (NDIM / TN), NTHREADS, SMEM_BYTES>>>(out);
}